// round 16
// baseline (speedup 1.0000x reference)
#include <cuda_runtime.h>
#include <cuda_bf16.h>
#include <cstdint>

#define N_TOKENS  16384
#define DIM       2048
#define NE        64
#define BM        64             // tokens per CTA
#define KT        64             // k per tile
#define NTILES    (DIM / KT)     // 32
#define THREADS   256
#define PK        72             // padded k per smem row (bf16 elems)
#define ROWB      (PK * 2)       // 144 bytes per row
#define PK32      (PK / 2)       // 36 uint32 per row

#define LVLA      (BM * ROWB)            // 9216
#define LVLB      (NE * ROWB)            // 9216
#define OFF_A     0
#define OFF_B     (3 * LVLA)             // 27648
#define STAGE_SZ  (OFF_B + 3 * LVLB)     // 55296
#define OFF_BIAS  (2 * STAGE_SZ)         // 110592
#define SMEM_TOTAL (OFF_BIAS + 256)      // 110848 -> 2 CTAs/SM
#define SC_PITCH  68

typedef uint32_t u32;

// precomputed 3-level bf16 split of W, [n][k] row-major
__device__ __nv_bfloat16 gW1[NE * DIM];
__device__ __nv_bfloat16 gW2[NE * DIM];
__device__ __nv_bfloat16 gW3[NE * DIM];

// exact truncation-based 3-way bf16 split of float2 -> 3 packed bf16x2
__device__ __forceinline__ void split3t(float2 f, u32& o1, u32& o2, u32& o3) {
    const u32 M = 0xFFFF0000u;
    u32 ax = __float_as_uint(f.x), ay = __float_as_uint(f.y);
    u32 hx1 = ax & M,              hy1 = ay & M;
    float rx1 = f.x - __uint_as_float(hx1);
    float ry1 = f.y - __uint_as_float(hy1);
    u32 hx2 = __float_as_uint(rx1) & M, hy2 = __float_as_uint(ry1) & M;
    float rx2 = rx1 - __uint_as_float(hx2);
    float ry2 = ry1 - __uint_as_float(hy2);
    u32 hx3 = __float_as_uint(rx2) & M, hy3 = __float_as_uint(ry2) & M;
    o1 = __byte_perm(hx1, hy1, 0x7632);
    o2 = __byte_perm(hx2, hy2, 0x7632);
    o3 = __byte_perm(hx3, hy3, 0x7632);
}

__device__ __forceinline__ void mma16816(float* d, const u32* a, const u32* b) {
    asm volatile(
        "mma.sync.aligned.m16n8k16.row.col.f32.bf16.bf16.f32 "
        "{%0,%1,%2,%3}, {%4,%5,%6,%7}, {%8,%9}, {%0,%1,%2,%3};"
        : "+f"(d[0]), "+f"(d[1]), "+f"(d[2]), "+f"(d[3])
        : "r"(a[0]), "r"(a[1]), "r"(a[2]), "r"(a[3]), "r"(b[0]), "r"(b[1]));
}

__device__ __forceinline__ void cp16(u32 dst, const void* src) {
    asm volatile("cp.async.ca.shared.global [%0], [%1], 16;" :: "r"(dst), "l"(src));
}
__device__ __forceinline__ void cp_commit() {
    asm volatile("cp.async.commit_group;" ::: "memory");
}
__device__ __forceinline__ void cp_wait0() {
    asm volatile("cp.async.wait_group 0;" ::: "memory");
}

// ---------------- prologue: split W once ----------------
__global__ void split_w_kernel(const float* __restrict__ W) {
    const int i = blockIdx.x * blockDim.x + threadIdx.x;   // float2 index
    if (i < NE * DIM / 2) {
        float2 f = ((const float2*)W)[i];
        u32 o1, o2, o3;
        split3t(f, o1, o2, o3);
        ((u32*)gW1)[i] = o1;
        ((u32*)gW2)[i] = o2;
        ((u32*)gW3)[i] = o3;
    }
}

// ---------------- main kernel ----------------
__global__ void __launch_bounds__(THREADS, 2)
topk_gate_hmma(const float* __restrict__ x, const float* __restrict__ b,
               float* __restrict__ out) {
    extern __shared__ char smem[];
    u32 sb;
    asm("{ .reg .u64 t; cvta.to.shared.u64 t, %1; cvt.u32.u64 %0, t; }"
        : "=r"(sb) : "l"(smem));

    const int tid  = threadIdx.x;
    const int lane = tid & 31;
    const int wid  = tid >> 5;          // 8 warps
    const int m0   = blockIdx.x * BM;

    // x-tile load geometry: 64 rows x 16 float4 = 1024 float4 / 256 thr = 4 each
    const int rb = tid >> 4;            // 0..15
    const int q  = tid & 15;            // float4 column

    float* bias = (float*)(smem + OFF_BIAS);
    if (tid < NE) bias[tid] = b[tid];

    float4 xr[4];
    auto ldg_tile = [&](int t) {
        const int k0f = t * KT + q * 4;
#pragma unroll
        for (int l = 0; l < 4; ++l)
            xr[l] = *(const float4*)&x[(size_t)(m0 + rb + l * 16) * DIM + k0f];
    };

    // async W copy: tile t -> stage (t&1); 1536 uint4 / 256 thr = 6 cp each
    auto issue_w = [&](int t) {
        const int k0 = t * KT;
        const u32 base = sb + (t & 1) * STAGE_SZ + OFF_B;
#pragma unroll
        for (int lv = 0; lv < 3; ++lv) {
            const __nv_bfloat16* src = (lv == 0) ? gW1 : (lv == 1) ? gW2 : gW3;
#pragma unroll
            for (int ii = 0; ii < 2; ++ii) {
                const int rem = tid + ii * 256;     // 0..511
                const int row = rem >> 3;           // 0..63
                const int q8  = rem & 7;
                cp16(base + lv * LVLB + row * ROWB + q8 * 16,
                     &src[row * DIM + k0 + q8 * 8]);
            }
        }
        cp_commit();
    };

    auto store_x = [&](char* stg) {
#pragma unroll
        for (int l = 0; l < 4; ++l) {
            const int byteoff = (rb + l * 16) * ROWB + q * 8;
            u32 a1, a2, a3, b1, b2, b3;
            split3t(make_float2(xr[l].x, xr[l].y), a1, a2, a3);
            split3t(make_float2(xr[l].z, xr[l].w), b1, b2, b3);
            *(uint2*)(stg + OFF_A + 0 * LVLA + byteoff) = make_uint2(a1, b1);
            *(uint2*)(stg + OFF_A + 1 * LVLA + byteoff) = make_uint2(a2, b2);
            *(uint2*)(stg + OFF_A + 2 * LVLA + byteoff) = make_uint2(a3, b3);
        }
    };

    // MMA geometry: 8 warps = 4 m-groups x 2 n-groups; warp = 16 tok x 32 exp
    const int g   = lane >> 2;
    const int tig = lane & 3;
    const int mw  = (wid >> 1) * 16;
    const int nw  = (wid & 1) * 32;
    const int ai0 = (mw + g) * PK32;
    const int ai1 = ai0 + 8 * PK32;

    float acc[4][4];
#pragma unroll
    for (int j = 0; j < 4; ++j)
#pragma unroll
        for (int r = 0; r < 4; ++r) acc[j][r] = 0.0f;

    ldg_tile(0);
    issue_w(0);

    for (int t = 0; t < NTILES; ++t) {
        char* stg = smem + (t & 1) * STAGE_SZ;
        store_x(stg);
        if (t + 1 < NTILES) ldg_tile(t + 1);
        cp_wait0();                       // W(t) landed
        __syncthreads();                  // everyone's W(t)+x(t) visible
        if (t + 1 < NTILES) issue_w(t + 1);   // other stage: safe past bar

        const u32* A1 = (const u32*)(stg + OFF_A);
        const u32* A2 = (const u32*)(stg + OFF_A + LVLA);
        const u32* A3 = (const u32*)(stg + OFF_A + 2 * LVLA);
        const u32* B1 = (const u32*)(stg + OFF_B);
        const u32* B2 = (const u32*)(stg + OFF_B + LVLB);
        const u32* B3 = (const u32*)(stg + OFF_B + 2 * LVLB);

#pragma unroll
        for (int ks = 0; ks < 4; ++ks) {
            const int o0 = ks * 8 + tig;
            const int o4 = o0 + 4;
            u32 a1[4], a2[4], a3[4];
            a1[0] = A1[ai0 + o0]; a1[1] = A1[ai1 + o0];
            a1[2] = A1[ai0 + o4]; a1[3] = A1[ai1 + o4];
            a2[0] = A2[ai0 + o0]; a2[1] = A2[ai1 + o0];
            a2[2] = A2[ai0 + o4]; a2[3] = A2[ai1 + o4];
            a3[0] = A3[ai0 + o0]; a3[1] = A3[ai1 + o0];
            a3[2] = A3[ai0 + o4]; a3[3] = A3[ai1 + o4];
#pragma unroll
            for (int j = 0; j < 4; ++j) {
                const int ni = (nw + j * 8 + g) * PK32;
                u32 b1[2], b2[2], b3[2];
                b1[0] = B1[ni + o0]; b1[1] = B1[ni + o4];
                b2[0] = B2[ni + o0]; b2[1] = B2[ni + o4];
                b3[0] = B3[ni + o0]; b3[1] = B3[ni + o4];
                mma16816(acc[j], a1, b1);
                mma16816(acc[j], a1, b2);
                mma16816(acc[j], a2, b1);
                mma16816(acc[j], a2, b2);
                mma16816(acc[j], a1, b3);
                mma16816(acc[j], a3, b1);
            }
        }
        // no trailing barrier: next store_x/issue_w target the other stage
    }
    __syncthreads();

    // ---------------- scores -> smem (aliases stage 0), + bias ----------------
    float* sc = (float*)smem;   // [BM][SC_PITCH] = 17408 B < STAGE_SZ
#pragma unroll
    for (int j = 0; j < 4; ++j) {
        const int n0 = nw + j * 8 + 2 * tig;
        sc[(mw + g) * SC_PITCH + n0]         = acc[j][0] + bias[n0];
        sc[(mw + g) * SC_PITCH + n0 + 1]     = acc[j][1] + bias[n0 + 1];
        sc[(mw + g + 8) * SC_PITCH + n0]     = acc[j][2] + bias[n0];
        sc[(mw + g + 8) * SC_PITCH + n0 + 1] = acc[j][3] + bias[n0 + 1];
    }
    __syncthreads();

    // ---------------- per-token top-2 + softmax renorm ----------------
    if (tid < BM) {
        const float* row = &sc[tid * SC_PITCH];
        float s[64];
        float m1 = -1e30f, m2 = -1e30f;
#pragma unroll
        for (int e = 0; e < 64; ++e) {
            const float v = row[e];
            s[e] = v;
            if (v > m1) { m2 = m1; m1 = v; }
            else if (v > m2) { m2 = v; }
        }
        float z = 0.0f;
#pragma unroll
        for (int e = 0; e < 64; ++e) z += __expf(s[e] - m1);

        const float denom = 1.0f + __expf(m2 - m1) + 1e-8f * z;
        const float inv   = 1.0f / denom;

        float* orow = out + (size_t)(m0 + tid) * NE;
#pragma unroll
        for (int e4 = 0; e4 < 16; ++e4) {
            float4 o;
            o.x = (s[e4 * 4 + 0] >= m2) ? __expf(s[e4 * 4 + 0] - m1) * inv : 0.0f;
            o.y = (s[e4 * 4 + 1] >= m2) ? __expf(s[e4 * 4 + 1] - m1) * inv : 0.0f;
            o.z = (s[e4 * 4 + 2] >= m2) ? __expf(s[e4 * 4 + 2] - m1) * inv : 0.0f;
            o.w = (s[e4 * 4 + 3] >= m2) ? __expf(s[e4 * 4 + 3] - m1) * inv : 0.0f;
            *(float4*)&orow[e4 * 4] = o;
        }
    }
}

extern "C" void kernel_launch(void* const* d_in, const int* in_sizes, int n_in,
                              void* d_out, int out_size) {
    const float* x = (const float*)d_in[0];
    const float* W = (const float*)d_in[1];
    const float* b = (const float*)d_in[2];
    float* out = (float*)d_out;
    cudaFuncSetAttribute(topk_gate_hmma,
                         cudaFuncAttributeMaxDynamicSharedMemorySize, SMEM_TOTAL);
    split_w_kernel<<<NE * DIM / 2 / 256, 256>>>(W);
    topk_gate_hmma<<<N_TOKENS / BM, THREADS, SMEM_TOTAL>>>(x, b, out);
}

// round 17
// speedup vs baseline: 1.1607x; 1.1607x over previous
#include <cuda_runtime.h>
#include <cuda_bf16.h>
#include <cstdint>

#define N_TOKENS  16384
#define DIM       2048
#define NE        64
#define BM        128            // tokens per CTA
#define KT        64             // k per tile
#define NTILES    (DIM / KT)     // 32
#define THREADS   256
#define PK        72             // padded k per smem row (bf16 elems)
#define ROWB      (PK * 2)       // 144 bytes per row
#define PK32      (PK / 2)       // 36 uint32 per row

// per-stage layout (3 split levels for A and B)
#define OFF_A1    0
#define OFF_A2    (OFF_A1 + BM * ROWB)   // 18432
#define OFF_A3    (OFF_A2 + BM * ROWB)   // 36864
#define OFF_B1    (OFF_A3 + BM * ROWB)   // 55296
#define OFF_B2    (OFF_B1 + NE * ROWB)   // 64512
#define OFF_B3    (OFF_B2 + NE * ROWB)   // 73728
#define STAGE_SZ  (OFF_B3 + NE * ROWB)   // 82944
#define OFF_BIAS  (2 * STAGE_SZ)         // 165888
#define SMEM_TOTAL (OFF_BIAS + 256)      // 166144
#define SC_PITCH  68

typedef uint32_t u32;

__device__ __forceinline__ u32 bits2(__nv_bfloat162 v) { return *(u32*)&v; }

// 3-way bf16 split of a float2 (exact residuals)
__device__ __forceinline__ void split3(float2 f, u32& o1, u32& o2, u32& o3) {
    __nv_bfloat162 h1 = __float22bfloat162_rn(f);
    float2 g1 = __bfloat1622float2(h1);
    float2 r1 = make_float2(f.x - g1.x, f.y - g1.y);
    __nv_bfloat162 h2 = __float22bfloat162_rn(r1);
    float2 g2 = __bfloat1622float2(h2);
    float2 r2 = make_float2(r1.x - g2.x, r1.y - g2.y);
    __nv_bfloat162 h3 = __float22bfloat162_rn(r2);
    o1 = bits2(h1); o2 = bits2(h2); o3 = bits2(h3);
}

__device__ __forceinline__ void mma16816(float* d, const u32* a, const u32* b) {
    asm volatile(
        "mma.sync.aligned.m16n8k16.row.col.f32.bf16.bf16.f32 "
        "{%0,%1,%2,%3}, {%4,%5,%6,%7}, {%8,%9}, {%0,%1,%2,%3};"
        : "+f"(d[0]), "+f"(d[1]), "+f"(d[2]), "+f"(d[3])
        : "r"(a[0]), "r"(a[1]), "r"(a[2]), "r"(a[3]), "r"(b[0]), "r"(b[1]));
}

__global__ void __launch_bounds__(THREADS, 1)
topk_gate_hmma(const float* __restrict__ x, const float* __restrict__ W,
               const float* __restrict__ b, float* __restrict__ out) {
    extern __shared__ char smem[];
    const int tid  = threadIdx.x;
    const int lane = tid & 31;
    const int wid  = tid >> 5;          // 8 warps
    const int m0   = blockIdx.x * BM;

    // tile-load geometry
    const int rb = tid >> 4;            // 0..15
    const int q  = tid & 15;            // float4 column

    float* bias = (float*)(smem + OFF_BIAS);
    if (tid < NE) bias[tid] = b[tid];

    float4 xr[8], wr[4];
    auto ldg_tile = [&](int t) {
        const int k0 = t * KT + q * 4;
#pragma unroll
        for (int l = 0; l < 8; ++l)
            xr[l] = *(const float4*)&x[(size_t)(m0 + rb + l * 16) * DIM + k0];
#pragma unroll
        for (int l = 0; l < 4; ++l)
            wr[l] = *(const float4*)&W[(size_t)(rb + l * 16) * DIM + k0];
    };

    auto split3_store = [&](float4 v, char* r1, char* r2, char* r3, int byteoff) {
        u32 a1, a2, a3, b1, b2, b3;
        split3(make_float2(v.x, v.y), a1, a2, a3);
        split3(make_float2(v.z, v.w), b1, b2, b3);
        *(uint2*)(r1 + byteoff) = make_uint2(a1, b1);
        *(uint2*)(r2 + byteoff) = make_uint2(a2, b2);
        *(uint2*)(r3 + byteoff) = make_uint2(a3, b3);
    };

    // MMA geometry: warp = 16 tokens x 64 experts
    const int g   = lane >> 2;
    const int tig = lane & 3;
    const int mw  = wid * 16;
    const int ai0 = (mw + g) * PK32;
    const int ai1 = (mw + g + 8) * PK32;

    float acc[8][4];
#pragma unroll
    for (int j = 0; j < 8; ++j)
#pragma unroll
        for (int r = 0; r < 4; ++r) acc[j][r] = 0.0f;

    ldg_tile(0);

    for (int t = 0; t < NTILES; ++t) {
        char* stg = smem + (t & 1) * STAGE_SZ;

        // ---- convert regs -> smem bf16 x3 levels
#pragma unroll
        for (int l = 0; l < 8; ++l)
            split3_store(xr[l], stg + OFF_A1, stg + OFF_A2, stg + OFF_A3,
                         (rb + l * 16) * ROWB + q * 8);
#pragma unroll
        for (int l = 0; l < 4; ++l)
            split3_store(wr[l], stg + OFF_B1, stg + OFF_B2, stg + OFF_B3,
                         (rb + l * 16) * ROWB + q * 8);

        if (t + 1 < NTILES) ldg_tile(t + 1);
        __syncthreads();

        const u32* A[3] = { (const u32*)(stg + OFF_A1),
                            (const u32*)(stg + OFF_A2),
                            (const u32*)(stg + OFF_A3) };
        const u32* B[3] = { (const u32*)(stg + OFF_B1),
                            (const u32*)(stg + OFF_B2),
                            (const u32*)(stg + OFF_B3) };

#pragma unroll
        for (int ks = 0; ks < 4; ++ks) {
            const int o0 = ks * 8 + tig;
            const int o4 = o0 + 4;

            // hoist ALL fragments for this ks
            u32 afr[3][4];
#pragma unroll
            for (int lv = 0; lv < 3; ++lv) {
                afr[lv][0] = A[lv][ai0 + o0];
                afr[lv][1] = A[lv][ai1 + o0];
                afr[lv][2] = A[lv][ai0 + o4];
                afr[lv][3] = A[lv][ai1 + o4];
            }
            u32 bfr[8][3][2];
#pragma unroll
            for (int j = 0; j < 8; ++j) {
                const int ni = (j * 8 + g) * PK32;
#pragma unroll
                for (int lv = 0; lv < 3; ++lv) {
                    bfr[j][lv][0] = B[lv][ni + o0];
                    bfr[j][lv][1] = B[lv][ni + o4];
                }
            }
            // product-outer / j-inner: consecutive MMAs hit different accumulators
#pragma unroll
            for (int p = 0; p < 6; ++p) {
                const int la = (p == 0 || p == 1 || p == 4) ? 0 : (p == 2 || p == 3) ? 1 : 2;
                const int lb = (p == 0 || p == 2 || p == 5) ? 0 : (p == 1 || p == 3) ? 1 : 2;
#pragma unroll
                for (int j = 0; j < 8; ++j)
                    mma16816(acc[j], afr[la], bfr[j][lb]);
            }
        }
        // no trailing barrier: next convert writes the other stage
    }
    __syncthreads();

    // ---------------- scores -> smem (aliases stage 0), + bias ----------------
    float* sc = (float*)smem;   // [BM][SC_PITCH] = 34816 B < STAGE_SZ
#pragma unroll
    for (int j = 0; j < 8; ++j) {
        const int n0 = j * 8 + 2 * tig;
        sc[(mw + g) * SC_PITCH + n0]         = acc[j][0] + bias[n0];
        sc[(mw + g) * SC_PITCH + n0 + 1]     = acc[j][1] + bias[n0 + 1];
        sc[(mw + g + 8) * SC_PITCH + n0]     = acc[j][2] + bias[n0];
        sc[(mw + g + 8) * SC_PITCH + n0 + 1] = acc[j][3] + bias[n0 + 1];
    }
    __syncthreads();

    // ---------------- per-token top-2 + softmax renorm ----------------
    if (tid < BM) {
        const float* row = &sc[tid * SC_PITCH];
        float s[64];
        float m1 = -1e30f, m2 = -1e30f;
#pragma unroll
        for (int e = 0; e < 64; ++e) {
            const float v = row[e];
            s[e] = v;
            if (v > m1) { m2 = m1; m1 = v; }
            else if (v > m2) { m2 = v; }
        }
        float z = 0.0f;
#pragma unroll
        for (int e = 0; e < 64; ++e) z += __expf(s[e] - m1);

        const float denom = 1.0f + __expf(m2 - m1) + 1e-8f * z;
        const float inv   = 1.0f / denom;

        float* orow = out + (size_t)(m0 + tid) * NE;
#pragma unroll
        for (int e4 = 0; e4 < 16; ++e4) {
            float4 o;
            o.x = (s[e4 * 4 + 0] >= m2) ? __expf(s[e4 * 4 + 0] - m1) * inv : 0.0f;
            o.y = (s[e4 * 4 + 1] >= m2) ? __expf(s[e4 * 4 + 1] - m1) * inv : 0.0f;
            o.z = (s[e4 * 4 + 2] >= m2) ? __expf(s[e4 * 4 + 2] - m1) * inv : 0.0f;
            o.w = (s[e4 * 4 + 3] >= m2) ? __expf(s[e4 * 4 + 3] - m1) * inv : 0.0f;
            *(float4*)&orow[e4 * 4] = o;
        }
    }
}

extern "C" void kernel_launch(void* const* d_in, const int* in_sizes, int n_in,
                              void* d_out, int out_size) {
    const float* x = (const float*)d_in[0];
    const float* W = (const float*)d_in[1];
    const float* b = (const float*)d_in[2];
    float* out = (float*)d_out;
    static int configured = 0;
    if (!configured) {
        cudaFuncSetAttribute(topk_gate_hmma,
                             cudaFuncAttributeMaxDynamicSharedMemorySize, SMEM_TOTAL);
        configured = 1;
    }
    topk_gate_hmma<<<N_TOKENS / BM, THREADS, SMEM_TOTAL>>>(x, W, b, out);
}